// round 14
// baseline (speedup 1.0000x reference)
#include <cuda_runtime.h>
#include <math.h>
#include <stdint.h>

#define Bq 1024
#define Nn 50
#define Hh 128
#define Tt 50
#define Gg 2
#define FULLMASK 0xffffffffu

// Scratch (allocation-free rule: __device__ globals)
__device__ float g_ctx[Bq * Nn * Hh];
__device__ float g_eg [Bq * Nn * Hh];
__device__ float g_ep [Bq * Nn * Hh];
__device__ float g_xw [(size_t)Bq * Nn * 512];  // context @ Wi
__device__ float g_xw0[512];                    // dec_init @ Wi

__device__ __forceinline__ float my_tanh(float x) {
    float e = __expf(2.0f * x);
    return 1.0f - __fdividef(2.0f, e + 1.0f);
}
__device__ __forceinline__ float my_sig(float x) {
    return __fdividef(1.0f, 1.0f + __expf(-x));
}

// Merged register-blocked GEMM: two weight-column chunks share each sctx load.
__device__ __forceinline__ void pre_gemm2(
    const float* __restrict__ Wa, int LDa, int cola, float* outA, int LDOa,
    const float* __restrict__ Wb, int LDb, int colb, float* outB, int LDOb,
    const float (*sctx)[128], int rbase, int jj, int row0)
{
    float accA[16], accB[16];
    #pragma unroll
    for (int r = 0; r < 16; r++) { accA[r] = 0.f; accB[r] = 0.f; }
    for (int k4 = 0; k4 < 32; k4++) {
        float wa0 = Wa[(4 * k4 + 0) * LDa + cola + jj];
        float wa1 = Wa[(4 * k4 + 1) * LDa + cola + jj];
        float wa2 = Wa[(4 * k4 + 2) * LDa + cola + jj];
        float wa3 = Wa[(4 * k4 + 3) * LDa + cola + jj];
        float wb0 = Wb[(4 * k4 + 0) * LDb + colb + jj];
        float wb1 = Wb[(4 * k4 + 1) * LDb + colb + jj];
        float wb2 = Wb[(4 * k4 + 2) * LDb + colb + jj];
        float wb3 = Wb[(4 * k4 + 3) * LDb + colb + jj];
        #pragma unroll
        for (int r = 0; r < 16; r++) {
            float4 c = reinterpret_cast<const float4*>(&sctx[rbase + r][0])[k4];
            accA[r] = fmaf(wa0, c.x, fmaf(wa1, c.y, fmaf(wa2, c.z, fmaf(wa3, c.w, accA[r]))));
            accB[r] = fmaf(wb0, c.x, fmaf(wb1, c.y, fmaf(wb2, c.z, fmaf(wb3, c.w, accB[r]))));
        }
    }
    #pragma unroll
    for (int r = 0; r < 16; r++) {
        outA[(size_t)(row0 + rbase + r) * LDOa + cola + jj] = accA[r];
        outB[(size_t)(row0 + rbase + r) * LDOb + colb + jj] = accB[r];
    }
}

// ---------------- Phase A: context, e_g, e_p, ctx@Wi ----------------
__global__ __launch_bounds__(512) void k_pre(
    const float* __restrict__ pnt, const float* __restrict__ Wemb,
    const float* __restrict__ bemb, const float* __restrict__ Wrg,
    const float* __restrict__ Wrp, const float* __restrict__ Wi,
    const float* __restrict__ dini)
{
    if (blockIdx.x == (Bq * Nn) / 64) {
        int j = threadIdx.x;
        float s = 0.f;
        #pragma unroll 4
        for (int k = 0; k < 128; k++) s = fmaf(dini[k], Wi[k * 512 + j], s);
        g_xw0[j] = s;
        return;
    }
    __shared__ __align__(16) float sctx[64][128];
    int row0 = blockIdx.x * 64;
    int tid = threadIdx.x;
    for (int i = tid; i < 64 * 128; i += 512) {
        int r = i >> 7, h = i & 127;
        int row = row0 + r;
        float px = pnt[row * 2 + 0], py = pnt[row * 2 + 1];
        float v = fmaf(px, Wemb[h], fmaf(py, Wemb[128 + h], bemb[h]));
        sctx[r][h] = v;
        g_ctx[(size_t)row * 128 + h] = v;
    }
    __syncthreads();
    int jj = tid & 127;
    int quarter = tid >> 7;
    int rbase = quarter * 16;

    pre_gemm2(Wrg, 128, 0,   g_eg, 128,  Wrp, 128, 0,   g_ep, 128, sctx, rbase, jj, row0);
    pre_gemm2(Wi,  512, 0,   g_xw, 512,  Wi,  512, 128, g_xw, 512, sctx, rbase, jj, row0);
    pre_gemm2(Wi,  512, 256, g_xw, 512,  Wi,  512, 384, g_xw, 512, sctx, rbase, jj, row0);
}

// ---------------- Phase B+C: full T-loop, 4 CTAs/SM ----------------
__global__ __launch_bounds__(256, 4) void k_main(
    const float* __restrict__ pnt, const float* __restrict__ Wh,
    const float* __restrict__ bl,
    const float* __restrict__ Wqg, const float* __restrict__ vg,
    const float* __restrict__ Wqp, const float* __restrict__ vp,
    const float* __restrict__ Wrc, const float* __restrict__ W1,
    const float* __restrict__ b1, const float* __restrict__ W2,
    const float* __restrict__ b2, float* __restrict__ out)
{
    int b0 = blockIdx.x * Gg;
    int tid = threadIdx.x;
    int lane = tid & 31, wid = tid >> 5;   // 8 warps
    int jj = tid & 127;
    int half = tid >> 7;                   // 0..1 : k-half (gates) / batch id (others)

    __shared__ __align__(16) float4 sh_part[2][Gg][128];        // 8 KB gates partials
    __shared__ __align__(16) float sh_h[Gg][128], sh_c[Gg][128];
    __shared__ __align__(16) float sh_q[Gg][128], sh_q2[Gg][128];
    __shared__ float sh_u[Gg][52], sh_mask[Gg][52];
    __shared__ __align__(16) float sh_vg[128], sh_vp[128];
    __shared__ int   sh_act[Gg];
    __shared__ float sh_px[Gg], sh_py[Gg], sh_fx[Gg], sh_fy[Gg], sh_R[Gg];

    {   // init (256 threads == Gg*128 exactly)
        sh_h[half][jj] = 0.f; sh_c[half][jj] = 0.f;
        if (tid < Gg * 52) sh_mask[tid / 52][tid % 52] = 0.f;
        if (tid < 128) { sh_vg[tid] = vg[tid]; sh_vp[tid] = vp[tid]; }
        if (tid < Gg) sh_R[tid] = 0.f;
    }
    __syncthreads();

    float* oR  = out;
    float* oV  = out + Bq;
    float* oLP = out + 2 * Bq;
    float* oA  = oLP + (size_t)Bq * Tt * Nn;
    float* oC  = oA  + (size_t)Bq * Tt;
    float* oP  = oC  + (size_t)Bq * Tt * 2;

    const float4* Wh4 = reinterpret_cast<const float4*>(Wh);
    // attention row ownership: rows wid + 8*i (12-13 rows per warp)
    int nrows = (wid < 4) ? 13 : 12;
    int myr = wid + 8 * lane;
    bool rvalid = (lane < nrows);
    int myb = myr >= Nn, myn = myr - (myb ? Nn : 0);

    for (int t = 0; t < Tt; t++) {
        // ---- P0: gates partials, 2-way k-split (both batches per thread, 8 FMA/LDG)
        {
            float4 a0 = make_float4(0.f, 0.f, 0.f, 0.f);
            float4 a1 = make_float4(0.f, 0.f, 0.f, 0.f);
            int k0 = half * 64;
            #pragma unroll 4
            for (int k = k0; k < k0 + 64; k++) {
                float4 wh = Wh4[k * 128 + jj];
                float h0 = sh_h[0][k], h1 = sh_h[1][k];
                a0.x = fmaf(wh.x, h0, a0.x); a0.y = fmaf(wh.y, h0, a0.y);
                a0.z = fmaf(wh.z, h0, a0.z); a0.w = fmaf(wh.w, h0, a0.w);
                a1.x = fmaf(wh.x, h1, a1.x); a1.y = fmaf(wh.y, h1, a1.y);
                a1.z = fmaf(wh.z, h1, a1.z); a1.w = fmaf(wh.w, h1, a1.w);
            }
            sh_part[half][0][jj] = a0;
            sh_part[half][1][jj] = a1;
        }
        __syncthreads();
        // ---- P1: fused reduce + x@Wi row + LSTM pointwise (thread = (b=half, j=jj))
        {
            int b = half, j = jj;
            const float* p0 = reinterpret_cast<const float*>(&sh_part[0][b][0]);
            const float* p1 = reinterpret_cast<const float*>(&sh_part[1][b][0]);
            const float* xw = (t == 0) ? g_xw0
                : g_xw + ((size_t)(b0 + b) * Nn + sh_act[b]) * 512;
            float gi = xw[j]       + p0[j]       + p1[j]       + bl[j];
            float gf = xw[128 + j] + p0[128 + j] + p1[128 + j] + bl[128 + j];
            float gg = xw[256 + j] + p0[256 + j] + p1[256 + j] + bl[256 + j];
            float go = xw[384 + j] + p0[384 + j] + p1[384 + j] + bl[384 + j];
            float c2 = my_sig(gf) * sh_c[b][j] + my_sig(gi) * my_tanh(gg);
            sh_c[b][j] = c2;
            sh_h[b][j] = my_sig(go) * my_tanh(c2);
        }
        __syncthreads();
        // ---- P3: q = h2 @ Wq_g (4 independent accumulator chains)
        {
            int b = half;
            float q0 = 0.f, q1 = 0.f, q2 = 0.f, q3 = 0.f;
            #pragma unroll 4
            for (int k = 0; k < 128; k += 4) {
                q0 = fmaf(Wqg[(k + 0) * 128 + jj], sh_h[b][k + 0], q0);
                q1 = fmaf(Wqg[(k + 1) * 128 + jj], sh_h[b][k + 1], q1);
                q2 = fmaf(Wqg[(k + 2) * 128 + jj], sh_h[b][k + 2], q2);
                q3 = fmaf(Wqg[(k + 3) * 128 + jj], sh_h[b][k + 3], q3);
            }
            sh_q[b][jj] = (q0 + q1) + (q2 + q3);
        }
        __syncthreads();
        // ---- P4: u = sum tanh(e_g+q)*v_g; masked rows skipped (underflow-exact)
        {
            float4 vv = reinterpret_cast<const float4*>(sh_vg)[lane];
            float mk = rvalid ? sh_mask[myb][myn] : 1.f;
            if (rvalid && mk != 0.f) sh_u[myb][myn] = -1e9f;
            unsigned um = __ballot_sync(FULLMASK, rvalid && mk == 0.f);
            while (um) {
                int i0 = __ffs(um) - 1; um &= um - 1;
                int rA = wid + 8 * i0;
                int bA = rA >= Nn, nA = rA - (bA ? Nn : 0);
                if (um) {
                    int i1 = __ffs(um) - 1; um &= um - 1;
                    int rB = wid + 8 * i1;
                    int bB = rB >= Nn, nB = rB - (bB ? Nn : 0);
                    float4 eA = reinterpret_cast<const float4*>(
                        g_eg + ((size_t)(b0 + bA) * Nn + nA) * 128)[lane];
                    float4 eB = reinterpret_cast<const float4*>(
                        g_eg + ((size_t)(b0 + bB) * Nn + nB) * 128)[lane];
                    float4 qA = reinterpret_cast<const float4*>(sh_q[bA])[lane];
                    float4 qB = reinterpret_cast<const float4*>(sh_q[bB])[lane];
                    float sA = my_tanh(eA.x + qA.x) * vv.x;
                    sA = fmaf(my_tanh(eA.y + qA.y), vv.y, sA);
                    sA = fmaf(my_tanh(eA.z + qA.z), vv.z, sA);
                    sA = fmaf(my_tanh(eA.w + qA.w), vv.w, sA);
                    float sB = my_tanh(eB.x + qB.x) * vv.x;
                    sB = fmaf(my_tanh(eB.y + qB.y), vv.y, sB);
                    sB = fmaf(my_tanh(eB.z + qB.z), vv.z, sB);
                    sB = fmaf(my_tanh(eB.w + qB.w), vv.w, sB);
                    #pragma unroll
                    for (int o = 16; o; o >>= 1) {
                        sA += __shfl_xor_sync(FULLMASK, sA, o);
                        sB += __shfl_xor_sync(FULLMASK, sB, o);
                    }
                    if (lane == 0) { sh_u[bA][nA] = sA; sh_u[bB][nB] = sB; }
                } else {
                    float4 e = reinterpret_cast<const float4*>(
                        g_eg + ((size_t)(b0 + bA) * Nn + nA) * 128)[lane];
                    float4 q = reinterpret_cast<const float4*>(sh_q[bA])[lane];
                    float s = my_tanh(e.x + q.x) * vv.x;
                    s = fmaf(my_tanh(e.y + q.y), vv.y, s);
                    s = fmaf(my_tanh(e.z + q.z), vv.z, s);
                    s = fmaf(my_tanh(e.w + q.w), vv.w, s);
                    #pragma unroll
                    for (int o = 16; o; o >>= 1) s += __shfl_xor_sync(FULLMASK, s, o);
                    if (lane == 0) sh_u[bA][nA] = s;
                }
            }
        }
        __syncthreads();
        // ---- P5: softmax(u) -> p (warp b handles batch b)
        if (wid < Gg) {
            int b = wid;
            float l0 = sh_u[b][lane];
            float l1 = (lane < 18) ? sh_u[b][lane + 32] : -1e38f;
            float m = fmaxf(l0, l1);
            #pragma unroll
            for (int o = 16; o; o >>= 1) m = fmaxf(m, __shfl_xor_sync(FULLMASK, m, o));
            float e0 = __expf(l0 - m);
            float e1 = (lane < 18) ? __expf(l1 - m) : 0.f;
            float s = e0 + e1;
            #pragma unroll
            for (int o = 16; o; o >>= 1) s += __shfl_xor_sync(FULLMASK, s, o);
            float inv = __fdividef(1.f, s);
            sh_u[b][lane] = e0 * inv;
            if (lane < 18) sh_u[b][lane + 32] = e1 * inv;
        }
        __syncthreads();
        // ---- P6: glimpse g = p @ e_g; skip masked n (p == 0 exactly via underflow)
        {
            int b = half;
            const float* ep = g_eg + ((size_t)(b0 + b) * Nn) * 128 + jj;
            unsigned m0 = __ballot_sync(FULLMASK, sh_mask[b][lane] == 0.f);
            unsigned m1 = __ballot_sync(FULLMASK, lane < 18 && sh_mask[b][lane + 32] == 0.f);
            float g0 = 0.f, g1 = 0.f, g2 = 0.f, g3 = 0.f;
            while (m0) {
                int n = __ffs(m0) - 1; m0 &= m0 - 1;
                g0 = fmaf(sh_u[b][n], ep[n * 128], g0);
                if (m0) {
                    int n2 = __ffs(m0) - 1; m0 &= m0 - 1;
                    g1 = fmaf(sh_u[b][n2], ep[n2 * 128], g1);
                }
            }
            while (m1) {
                int n = 32 + __ffs(m1) - 1; m1 &= m1 - 1;
                g2 = fmaf(sh_u[b][n], ep[n * 128], g2);
                if (m1) {
                    int n2 = 32 + __ffs(m1) - 1; m1 &= m1 - 1;
                    g3 = fmaf(sh_u[b][n2], ep[n2 * 128], g3);
                }
            }
            sh_q[b][jj] = (g0 + g1) + (g2 + g3);
        }
        __syncthreads();
        // ---- P7: q2 = g @ Wq_p (4 accumulators)
        {
            int b = half;
            float q0 = 0.f, q1 = 0.f, q2 = 0.f, q3 = 0.f;
            #pragma unroll 4
            for (int k = 0; k < 128; k += 4) {
                q0 = fmaf(Wqp[(k + 0) * 128 + jj], sh_q[b][k + 0], q0);
                q1 = fmaf(Wqp[(k + 1) * 128 + jj], sh_q[b][k + 1], q1);
                q2 = fmaf(Wqp[(k + 2) * 128 + jj], sh_q[b][k + 2], q2);
                q3 = fmaf(Wqp[(k + 3) * 128 + jj], sh_q[b][k + 3], q3);
            }
            sh_q2[b][jj] = (q0 + q1) + (q2 + q3);
        }
        __syncthreads();
        // ---- P8: logit = 10*tanh(u2); masked rows -> -1e9 (1e-8 rel on oLP)
        {
            float4 vv = reinterpret_cast<const float4*>(sh_vp)[lane];
            float mk = rvalid ? sh_mask[myb][myn] : 1.f;
            if (rvalid && mk != 0.f) sh_u[myb][myn] = -1e9f;
            unsigned um = __ballot_sync(FULLMASK, rvalid && mk == 0.f);
            while (um) {
                int i0 = __ffs(um) - 1; um &= um - 1;
                int rA = wid + 8 * i0;
                int bA = rA >= Nn, nA = rA - (bA ? Nn : 0);
                if (um) {
                    int i1 = __ffs(um) - 1; um &= um - 1;
                    int rB = wid + 8 * i1;
                    int bB = rB >= Nn, nB = rB - (bB ? Nn : 0);
                    float4 eA = reinterpret_cast<const float4*>(
                        g_ep + ((size_t)(b0 + bA) * Nn + nA) * 128)[lane];
                    float4 eB = reinterpret_cast<const float4*>(
                        g_ep + ((size_t)(b0 + bB) * Nn + nB) * 128)[lane];
                    float4 qA = reinterpret_cast<const float4*>(sh_q2[bA])[lane];
                    float4 qB = reinterpret_cast<const float4*>(sh_q2[bB])[lane];
                    float sA = my_tanh(eA.x + qA.x) * vv.x;
                    sA = fmaf(my_tanh(eA.y + qA.y), vv.y, sA);
                    sA = fmaf(my_tanh(eA.z + qA.z), vv.z, sA);
                    sA = fmaf(my_tanh(eA.w + qA.w), vv.w, sA);
                    float sB = my_tanh(eB.x + qB.x) * vv.x;
                    sB = fmaf(my_tanh(eB.y + qB.y), vv.y, sB);
                    sB = fmaf(my_tanh(eB.z + qB.z), vv.z, sB);
                    sB = fmaf(my_tanh(eB.w + qB.w), vv.w, sB);
                    #pragma unroll
                    for (int o = 16; o; o >>= 1) {
                        sA += __shfl_xor_sync(FULLMASK, sA, o);
                        sB += __shfl_xor_sync(FULLMASK, sB, o);
                    }
                    if (lane == 0) {
                        sh_u[bA][nA] = 10.0f * my_tanh(sA);
                        sh_u[bB][nB] = 10.0f * my_tanh(sB);
                    }
                } else {
                    float4 e = reinterpret_cast<const float4*>(
                        g_ep + ((size_t)(b0 + bA) * Nn + nA) * 128)[lane];
                    float4 q = reinterpret_cast<const float4*>(sh_q2[bA])[lane];
                    float s = my_tanh(e.x + q.x) * vv.x;
                    s = fmaf(my_tanh(e.y + q.y), vv.y, s);
                    s = fmaf(my_tanh(e.z + q.z), vv.z, s);
                    s = fmaf(my_tanh(e.w + q.w), vv.w, s);
                    #pragma unroll
                    for (int o = 16; o; o >>= 1) s += __shfl_xor_sync(FULLMASK, s, o);
                    if (lane == 0) sh_u[bA][nA] = 10.0f * my_tanh(s);
                }
            }
        }
        __syncthreads();
        // ---- P9: log_softmax / softmax / argmax / outputs / state
        if (wid < Gg) {
            int b = wid; int gb = b0 + b;
            float l0 = sh_u[b][lane];
            float l1 = (lane < 18) ? sh_u[b][lane + 32] : -1e38f;
            float m = fmaxf(l0, l1);
            #pragma unroll
            for (int o = 16; o; o >>= 1) m = fmaxf(m, __shfl_xor_sync(FULLMASK, m, o));
            float e0 = __expf(l0 - m);
            float e1 = (lane < 18) ? __expf(l1 - m) : 0.f;
            float s = e0 + e1;
            #pragma unroll
            for (int o = 16; o; o >>= 1) s += __shfl_xor_sync(FULLMASK, s, o);
            float lgs = logf(s);
            float p0 = e0 / s;
            float p1 = e1 / s;
            size_t base = ((size_t)gb * Tt + t) * Nn;
            oLP[base + lane] = (l0 - m) - lgs;
            oP [base + lane] = p0;
            if (lane < 18) {
                oLP[base + lane + 32] = (l1 - m) - lgs;
                oP [base + lane + 32] = p1;
            }
            float bv = p0; int bi = lane;
            if (lane < 18 && p1 > bv) { bv = p1; bi = lane + 32; }
            #pragma unroll
            for (int o = 16; o; o >>= 1) {
                float ov = __shfl_down_sync(FULLMASK, bv, o);
                int   oi = __shfl_down_sync(FULLMASK, bi, o);
                if (ov > bv || (ov == bv && oi < bi)) { bv = ov; bi = oi; }
            }
            if (lane == 0) {
                int a = bi;
                sh_act[b] = a;
                sh_mask[b][a] = 1.0f;
                oA[(size_t)gb * Tt + t] = (float)a;
                float cx = pnt[((size_t)gb * Nn + a) * 2 + 0];
                float cy = pnt[((size_t)gb * Nn + a) * 2 + 1];
                oC[((size_t)gb * Tt + t) * 2 + 0] = cx;
                oC[((size_t)gb * Tt + t) * 2 + 1] = cy;
                if (t == 0) { sh_fx[b] = cx; sh_fy[b] = cy; }
                else {
                    float dx = cx - sh_px[b], dy = cy - sh_py[b];
                    sh_R[b] += sqrtf(dx * dx + dy * dy + 1e-10f);
                }
                sh_px[b] = cx; sh_py[b] = cy;
            }
        }
        __syncthreads();
    } // t loop

    // ---- R closing edge
    if (tid < Gg) {
        int b = tid; int gb = b0 + b;
        float dx = sh_fx[b] - sh_px[b], dy = sh_fy[b] - sh_py[b];
        oR[gb] = sh_R[b] + sqrtf(dx * dx + dy * dy + 1e-10f);
    }
    // ---- dec_last = context[b, last action]  (reuse sh_h)
    sh_h[half][jj] = g_ctx[((size_t)(b0 + half) * Nn + sh_act[half]) * 128 + jj];
    __syncthreads();
    // ---- critic shortcut: hy = dec_last @ Wref_c (softmax over length-1 enc == 1)
    {
        int b = half;
        float ha = 0.f, hb = 0.f;
        #pragma unroll 4
        for (int k = 0; k < 128; k += 2) {
            ha = fmaf(Wrc[k * 128 + jj],       sh_h[b][k],     ha);
            hb = fmaf(Wrc[(k + 1) * 128 + jj], sh_h[b][k + 1], hb);
        }
        sh_q[b][jj] = ha + hb;
    }
    __syncthreads();
    {
        int b = half;
        float za = 0.f, zb = 0.f;
        #pragma unroll 4
        for (int k = 0; k < 128; k += 2) {
            za = fmaf(W1[k * 128 + jj],       sh_q[b][k],     za);
            zb = fmaf(W1[(k + 1) * 128 + jj], sh_q[b][k + 1], zb);
        }
        sh_q2[b][jj] = fmaxf(za + zb + b1[jj], 0.f);
    }
    __syncthreads();
    if (wid < Gg) {
        int b = wid; int gb = b0 + b;
        float4 zq = reinterpret_cast<const float4*>(sh_q2[b])[lane];
        float4 w2 = reinterpret_cast<const float4*>(W2)[lane];
        float s = zq.x * w2.x + zq.y * w2.y + zq.z * w2.z + zq.w * w2.w;
        #pragma unroll
        for (int o = 16; o; o >>= 1) s += __shfl_xor_sync(FULLMASK, s, o);
        if (lane == 0) oV[gb] = s + b2[0];
    }
}

extern "C" void kernel_launch(void* const* d_in, const int* in_sizes, int n_in,
                              void* d_out, int out_size) {
    const float* pnt  = (const float*)d_in[0];
    const float* Wemb = (const float*)d_in[1];
    const float* bemb = (const float*)d_in[2];
    const float* dini = (const float*)d_in[3];
    const float* Wi   = (const float*)d_in[4];
    const float* Wh   = (const float*)d_in[5];
    const float* bl   = (const float*)d_in[6];
    const float* Wqg  = (const float*)d_in[7];
    const float* Wrg  = (const float*)d_in[8];
    const float* vg   = (const float*)d_in[9];
    const float* Wqp  = (const float*)d_in[10];
    const float* Wrp  = (const float*)d_in[11];
    const float* vp   = (const float*)d_in[12];
    // d_in[13..16]: Wi_c, Wh_c, b_c, Wq_c — dead (softmax over length-1 enc)
    const float* Wrc  = (const float*)d_in[17];
    // d_in[18]: v_c — dead
    const float* W1   = (const float*)d_in[19];
    const float* b1   = (const float*)d_in[20];
    const float* W2   = (const float*)d_in[21];
    const float* b2   = (const float*)d_in[22];

    k_pre<<<(Bq * Nn) / 64 + 1, 512>>>(pnt, Wemb, bemb, Wrg, Wrp, Wi, dini);
    k_main<<<Bq / Gg, 256>>>(pnt, Wh, bl, Wqg, vg, Wqp, vp,
                             Wrc, W1, b1, W2, b2, (float*)d_out);
}

// round 15
// speedup vs baseline: 1.8586x; 1.8586x over previous
#include <cuda_runtime.h>
#include <math.h>
#include <stdint.h>

#define Bq 1024
#define Nn 50
#define Hh 128
#define Tt 50
#define Gg 2
#define FULLMASK 0xffffffffu

// Factorization scratch (context is rank-2+bias in the 2D points)
__device__ float g_fg [3 * 128];   // Ag,Bg,Cg   : {Wemb0,Wemb1,bemb} @ Wref_g
__device__ float g_fp [3 * 128];   // Ap,Bp,Cp   : @ Wref_p
__device__ float g_fq [3 * 128];   // Agp,Bgp,Cgp: {Ag,Bg,Cg} @ Wq_p
__device__ float g_frc[3 * 128];   // Arc,Brc,Crc: @ Wref_c (critic)
__device__ float g_fi [3 * 512];   // Ai,Bi,Ci   : @ Wi
__device__ float g_xw0[512];       // dec_init @ Wi

__device__ __forceinline__ float my_tanh(float x) {
    float e = __expf(2.0f * x);
    return 1.0f - __fdividef(2.0f, e + 1.0f);
}
__device__ __forceinline__ float my_sig(float x) {
    return __fdividef(1.0f, 1.0f + __expf(-x));
}

// ---------------- tiny precompute: all factor vectors ----------------
__global__ __launch_bounds__(512) void k_pre2(
    const float* __restrict__ Wemb, const float* __restrict__ bemb,
    const float* __restrict__ Wrg,  const float* __restrict__ Wrp,
    const float* __restrict__ Wi,   const float* __restrict__ Wqp,
    const float* __restrict__ Wrc,  const float* __restrict__ dini)
{
    __shared__ float sF[3][128];   // Ag,Bg,Cg for stage 2
    int tid = threadIdx.x;
    // stage 1: 128-col outputs vs Wrg / Wrp / Wrc
    for (int idx = tid; idx < 3 * 128; idx += 512) {
        int s = idx >> 7, j = idx & 127;
        const float* src = (s == 0) ? Wemb : (s == 1) ? (Wemb + 128) : bemb;
        float ag = 0.f, ap = 0.f, ac = 0.f;
        #pragma unroll 4
        for (int k = 0; k < 128; k++) {
            float v = src[k];
            ag = fmaf(v, Wrg[k * 128 + j], ag);
            ap = fmaf(v, Wrp[k * 128 + j], ap);
            ac = fmaf(v, Wrc[k * 128 + j], ac);
        }
        g_fg[idx] = ag; sF[s][j] = ag;
        g_fp[idx] = ap;
        g_frc[idx] = ac;
    }
    // Wi factors (512-wide) and xw0
    for (int idx = tid; idx < 3 * 512; idx += 512) {
        int s = idx >> 9, j = idx & 511;
        const float* src = (s == 0) ? Wemb : (s == 1) ? (Wemb + 128) : bemb;
        float a = 0.f;
        #pragma unroll 4
        for (int k = 0; k < 128; k++) a = fmaf(src[k], Wi[k * 512 + j], a);
        g_fi[idx] = a;
    }
    {
        int j = tid;
        float a = 0.f;
        #pragma unroll 4
        for (int k = 0; k < 128; k++) a = fmaf(dini[k], Wi[k * 512 + j], a);
        g_xw0[j] = a;
    }
    __syncthreads();
    // stage 2: glimpse-through-Wqp factors
    for (int idx = tid; idx < 3 * 128; idx += 512) {
        int s = idx >> 7, j = idx & 127;
        float a = 0.f;
        #pragma unroll 4
        for (int k = 0; k < 128; k++) a = fmaf(sF[s][k], Wqp[k * 128 + j], a);
        g_fq[idx] = a;
    }
}

// ---------------- Phase B+C: full T-loop, 4 CTAs/SM ----------------
__global__ __launch_bounds__(256, 4) void k_main(
    const float* __restrict__ pnt, const float* __restrict__ Wh,
    const float* __restrict__ bl,
    const float* __restrict__ Wqg, const float* __restrict__ vg,
    const float* __restrict__ vp,  const float* __restrict__ W1,
    const float* __restrict__ b1,  const float* __restrict__ W2,
    const float* __restrict__ b2,  float* __restrict__ out)
{
    int b0 = blockIdx.x * Gg;
    int tid = threadIdx.x;
    int lane = tid & 31, wid = tid >> 5;   // 8 warps
    int jj = tid & 127;
    int half = tid >> 7;                   // 0..1 : k-half (gates) / batch id (others)

    __shared__ __align__(16) float4 sh_part[2][Gg][128];        // 8 KB gates partials
    __shared__ __align__(16) float sh_h[Gg][128], sh_c[Gg][128];
    __shared__ __align__(16) float sh_q[Gg][128], sh_q2[Gg][128];
    __shared__ float sh_u[Gg][52], sh_mask[Gg][52];
    __shared__ __align__(16) float sh_vg[128], sh_vp[128];
    __shared__ __align__(16) float sh_fg[3][128], sh_fp[3][128], sh_fq[3][128];
    __shared__ __align__(16) float sh_fi[3][512];
    __shared__ __align__(8)  float2 sh_p[Gg][52];
    __shared__ int   sh_act[Gg];
    __shared__ float sh_sx[Gg], sh_sy[Gg];
    __shared__ float sh_px[Gg], sh_py[Gg], sh_fx[Gg], sh_fy[Gg], sh_R[Gg];

    {   // init
        sh_h[half][jj] = 0.f; sh_c[half][jj] = 0.f;
        if (tid < Gg * 52) sh_mask[tid / 52][tid % 52] = 0.f;
        if (tid < 128) {
            sh_vg[tid] = vg[tid]; sh_vp[tid] = vp[tid];
            #pragma unroll
            for (int s = 0; s < 3; s++) {
                sh_fg[s][tid] = g_fg[s * 128 + tid];
                sh_fp[s][tid] = g_fp[s * 128 + tid];
                sh_fq[s][tid] = g_fq[s * 128 + tid];
            }
        }
        for (int i = tid; i < 3 * 512; i += 256) sh_fi[i >> 9][i & 511] = g_fi[i];
        for (int i = tid; i < Gg * Nn; i += 256) {
            int b = i / Nn, n = i - b * Nn;
            sh_p[b][n] = reinterpret_cast<const float2*>(pnt)[(size_t)(b0 + b) * Nn + n];
        }
        if (tid < Gg) sh_R[tid] = 0.f;
    }
    __syncthreads();

    float* oR  = out;
    float* oV  = out + Bq;
    float* oLP = out + 2 * Bq;
    float* oA  = oLP + (size_t)Bq * Tt * Nn;
    float* oC  = oA  + (size_t)Bq * Tt;
    float* oP  = oC  + (size_t)Bq * Tt * 2;

    const float4* Wh4 = reinterpret_cast<const float4*>(Wh);
    // attention row ownership: rows wid + 8*i (12-13 rows per warp)
    int nrows = (wid < 4) ? 13 : 12;
    int myr = wid + 8 * lane;
    bool rvalid = (lane < nrows);
    int myb = myr >= Nn, myn = myr - (myb ? Nn : 0);

    for (int t = 0; t < Tt; t++) {
        // ---- P0: gates partials, 2-way k-split (both batches per thread, 8 FMA/LDG)
        {
            float4 a0 = make_float4(0.f, 0.f, 0.f, 0.f);
            float4 a1 = make_float4(0.f, 0.f, 0.f, 0.f);
            int k0 = half * 64;
            #pragma unroll 4
            for (int k = k0; k < k0 + 64; k++) {
                float4 wh = Wh4[k * 128 + jj];
                float h0 = sh_h[0][k], h1 = sh_h[1][k];
                a0.x = fmaf(wh.x, h0, a0.x); a0.y = fmaf(wh.y, h0, a0.y);
                a0.z = fmaf(wh.z, h0, a0.z); a0.w = fmaf(wh.w, h0, a0.w);
                a1.x = fmaf(wh.x, h1, a1.x); a1.y = fmaf(wh.y, h1, a1.y);
                a1.z = fmaf(wh.z, h1, a1.z); a1.w = fmaf(wh.w, h1, a1.w);
            }
            sh_part[half][0][jj] = a0;
            sh_part[half][1][jj] = a1;
        }
        __syncthreads();
        // ---- P1: fused reduce + factored x@Wi + LSTM pointwise (thread = (b=half, j=jj))
        {
            int b = half, j = jj;
            const float* p0 = reinterpret_cast<const float*>(&sh_part[0][b][0]);
            const float* p1 = reinterpret_cast<const float*>(&sh_part[1][b][0]);
            float xi, xf, xg, xo;
            if (t == 0) {
                xi = g_xw0[j]; xf = g_xw0[128 + j]; xg = g_xw0[256 + j]; xo = g_xw0[384 + j];
            } else {
                float pxa = sh_px[b], pya = sh_py[b];
                xi = fmaf(pxa, sh_fi[0][j],       fmaf(pya, sh_fi[1][j],       sh_fi[2][j]));
                xf = fmaf(pxa, sh_fi[0][128 + j], fmaf(pya, sh_fi[1][128 + j], sh_fi[2][128 + j]));
                xg = fmaf(pxa, sh_fi[0][256 + j], fmaf(pya, sh_fi[1][256 + j], sh_fi[2][256 + j]));
                xo = fmaf(pxa, sh_fi[0][384 + j], fmaf(pya, sh_fi[1][384 + j], sh_fi[2][384 + j]));
            }
            float gi = xi + p0[j]       + p1[j]       + bl[j];
            float gf = xf + p0[128 + j] + p1[128 + j] + bl[128 + j];
            float gg = xg + p0[256 + j] + p1[256 + j] + bl[256 + j];
            float go = xo + p0[384 + j] + p1[384 + j] + bl[384 + j];
            float c2 = my_sig(gf) * sh_c[b][j] + my_sig(gi) * my_tanh(gg);
            sh_c[b][j] = c2;
            sh_h[b][j] = my_sig(go) * my_tanh(c2);
        }
        __syncthreads();
        // ---- P3: q = h2 @ Wq_g (4 independent accumulator chains)
        {
            int b = half;
            float q0 = 0.f, q1 = 0.f, q2 = 0.f, q3 = 0.f;
            #pragma unroll 4
            for (int k = 0; k < 128; k += 4) {
                q0 = fmaf(Wqg[(k + 0) * 128 + jj], sh_h[b][k + 0], q0);
                q1 = fmaf(Wqg[(k + 1) * 128 + jj], sh_h[b][k + 1], q1);
                q2 = fmaf(Wqg[(k + 2) * 128 + jj], sh_h[b][k + 2], q2);
                q3 = fmaf(Wqg[(k + 3) * 128 + jj], sh_h[b][k + 3], q3);
            }
            sh_q[b][jj] = (q0 + q1) + (q2 + q3);
        }
        __syncthreads();
        // ---- P4: u = sum tanh(e_g+q)*v_g with e_g computed on the fly (no loads)
        {
            float4 fA = reinterpret_cast<const float4*>(sh_fg[0])[lane];
            float4 fB = reinterpret_cast<const float4*>(sh_fg[1])[lane];
            float4 fC = reinterpret_cast<const float4*>(sh_fg[2])[lane];
            float4 vv = reinterpret_cast<const float4*>(sh_vg)[lane];
            float mk = rvalid ? sh_mask[myb][myn] : 1.f;
            if (rvalid && mk != 0.f) sh_u[myb][myn] = -1e9f;   // exp underflow-exact
            unsigned um = __ballot_sync(FULLMASK, rvalid && mk == 0.f);
            while (um) {
                int i0 = __ffs(um) - 1; um &= um - 1;
                int rA = wid + 8 * i0;
                int bA = rA >= Nn, nA = rA - (bA ? Nn : 0);
                float2 cA = sh_p[bA][nA];
                float4 qA = reinterpret_cast<const float4*>(sh_q[bA])[lane];
                if (um) {
                    int i1 = __ffs(um) - 1; um &= um - 1;
                    int rB = wid + 8 * i1;
                    int bB = rB >= Nn, nB = rB - (bB ? Nn : 0);
                    float2 cB = sh_p[bB][nB];
                    float4 qB = reinterpret_cast<const float4*>(sh_q[bB])[lane];
                    float sA = my_tanh(fmaf(cA.x, fA.x, fmaf(cA.y, fB.x, fC.x)) + qA.x) * vv.x;
                    sA = fmaf(my_tanh(fmaf(cA.x, fA.y, fmaf(cA.y, fB.y, fC.y)) + qA.y), vv.y, sA);
                    sA = fmaf(my_tanh(fmaf(cA.x, fA.z, fmaf(cA.y, fB.z, fC.z)) + qA.z), vv.z, sA);
                    sA = fmaf(my_tanh(fmaf(cA.x, fA.w, fmaf(cA.y, fB.w, fC.w)) + qA.w), vv.w, sA);
                    float sB = my_tanh(fmaf(cB.x, fA.x, fmaf(cB.y, fB.x, fC.x)) + qB.x) * vv.x;
                    sB = fmaf(my_tanh(fmaf(cB.x, fA.y, fmaf(cB.y, fB.y, fC.y)) + qB.y), vv.y, sB);
                    sB = fmaf(my_tanh(fmaf(cB.x, fA.z, fmaf(cB.y, fB.z, fC.z)) + qB.z), vv.z, sB);
                    sB = fmaf(my_tanh(fmaf(cB.x, fA.w, fmaf(cB.y, fB.w, fC.w)) + qB.w), vv.w, sB);
                    #pragma unroll
                    for (int o = 16; o; o >>= 1) {
                        sA += __shfl_xor_sync(FULLMASK, sA, o);
                        sB += __shfl_xor_sync(FULLMASK, sB, o);
                    }
                    if (lane == 0) { sh_u[bA][nA] = sA; sh_u[bB][nB] = sB; }
                } else {
                    float sA = my_tanh(fmaf(cA.x, fA.x, fmaf(cA.y, fB.x, fC.x)) + qA.x) * vv.x;
                    sA = fmaf(my_tanh(fmaf(cA.x, fA.y, fmaf(cA.y, fB.y, fC.y)) + qA.y), vv.y, sA);
                    sA = fmaf(my_tanh(fmaf(cA.x, fA.z, fmaf(cA.y, fB.z, fC.z)) + qA.z), vv.z, sA);
                    sA = fmaf(my_tanh(fmaf(cA.x, fA.w, fmaf(cA.y, fB.w, fC.w)) + qA.w), vv.w, sA);
                    #pragma unroll
                    for (int o = 16; o; o >>= 1) sA += __shfl_xor_sync(FULLMASK, sA, o);
                    if (lane == 0) sh_u[bA][nA] = sA;
                }
            }
        }
        __syncthreads();
        // ---- P5: softmax(u) -> p, plus sx=sum(p*px), sy=sum(p*py) for the glimpse
        if (wid < Gg) {
            int b = wid;
            float l0 = sh_u[b][lane];
            float l1 = (lane < 18) ? sh_u[b][lane + 32] : -1e38f;
            float m = fmaxf(l0, l1);
            #pragma unroll
            for (int o = 16; o; o >>= 1) m = fmaxf(m, __shfl_xor_sync(FULLMASK, m, o));
            float e0 = __expf(l0 - m);
            float e1 = (lane < 18) ? __expf(l1 - m) : 0.f;
            float s = e0 + e1;
            #pragma unroll
            for (int o = 16; o; o >>= 1) s += __shfl_xor_sync(FULLMASK, s, o);
            float inv = __fdividef(1.f, s);
            float p0 = e0 * inv, p1 = e1 * inv;
            sh_u[b][lane] = p0;
            if (lane < 18) sh_u[b][lane + 32] = p1;
            float2 pp0 = sh_p[b][lane];
            float sx = p0 * pp0.x, sy = p0 * pp0.y;
            if (lane < 18) {
                float2 pp1 = sh_p[b][lane + 32];
                sx = fmaf(p1, pp1.x, sx);
                sy = fmaf(p1, pp1.y, sy);
            }
            #pragma unroll
            for (int o = 16; o; o >>= 1) {
                sx += __shfl_xor_sync(FULLMASK, sx, o);
                sy += __shfl_xor_sync(FULLMASK, sy, o);
            }
            if (lane == 0) { sh_sx[b] = sx; sh_sy[b] = sy; }
        }
        __syncthreads();
        // ---- P6+P7 fused: q2 = sx*(Ag@Wqp) + sy*(Bg@Wqp) + (Cg@Wqp)
        {
            int b = half;
            sh_q2[b][jj] = fmaf(sh_sx[b], sh_fq[0][jj],
                           fmaf(sh_sy[b], sh_fq[1][jj], sh_fq[2][jj]));
        }
        __syncthreads();
        // ---- P8: logit = 10*tanh(u2), e_p on the fly; masked rows -> -1e9
        {
            float4 fA = reinterpret_cast<const float4*>(sh_fp[0])[lane];
            float4 fB = reinterpret_cast<const float4*>(sh_fp[1])[lane];
            float4 fC = reinterpret_cast<const float4*>(sh_fp[2])[lane];
            float4 vv = reinterpret_cast<const float4*>(sh_vp)[lane];
            float mk = rvalid ? sh_mask[myb][myn] : 1.f;
            if (rvalid && mk != 0.f) sh_u[myb][myn] = -1e9f;
            unsigned um = __ballot_sync(FULLMASK, rvalid && mk == 0.f);
            while (um) {
                int i0 = __ffs(um) - 1; um &= um - 1;
                int rA = wid + 8 * i0;
                int bA = rA >= Nn, nA = rA - (bA ? Nn : 0);
                float2 cA = sh_p[bA][nA];
                float4 qA = reinterpret_cast<const float4*>(sh_q2[bA])[lane];
                if (um) {
                    int i1 = __ffs(um) - 1; um &= um - 1;
                    int rB = wid + 8 * i1;
                    int bB = rB >= Nn, nB = rB - (bB ? Nn : 0);
                    float2 cB = sh_p[bB][nB];
                    float4 qB = reinterpret_cast<const float4*>(sh_q2[bB])[lane];
                    float sA = my_tanh(fmaf(cA.x, fA.x, fmaf(cA.y, fB.x, fC.x)) + qA.x) * vv.x;
                    sA = fmaf(my_tanh(fmaf(cA.x, fA.y, fmaf(cA.y, fB.y, fC.y)) + qA.y), vv.y, sA);
                    sA = fmaf(my_tanh(fmaf(cA.x, fA.z, fmaf(cA.y, fB.z, fC.z)) + qA.z), vv.z, sA);
                    sA = fmaf(my_tanh(fmaf(cA.x, fA.w, fmaf(cA.y, fB.w, fC.w)) + qA.w), vv.w, sA);
                    float sB = my_tanh(fmaf(cB.x, fA.x, fmaf(cB.y, fB.x, fC.x)) + qB.x) * vv.x;
                    sB = fmaf(my_tanh(fmaf(cB.x, fA.y, fmaf(cB.y, fB.y, fC.y)) + qB.y), vv.y, sB);
                    sB = fmaf(my_tanh(fmaf(cB.x, fA.z, fmaf(cB.y, fB.z, fC.z)) + qB.z), vv.z, sB);
                    sB = fmaf(my_tanh(fmaf(cB.x, fA.w, fmaf(cB.y, fB.w, fC.w)) + qB.w), vv.w, sB);
                    #pragma unroll
                    for (int o = 16; o; o >>= 1) {
                        sA += __shfl_xor_sync(FULLMASK, sA, o);
                        sB += __shfl_xor_sync(FULLMASK, sB, o);
                    }
                    if (lane == 0) {
                        sh_u[bA][nA] = 10.0f * my_tanh(sA);
                        sh_u[bB][nB] = 10.0f * my_tanh(sB);
                    }
                } else {
                    float sA = my_tanh(fmaf(cA.x, fA.x, fmaf(cA.y, fB.x, fC.x)) + qA.x) * vv.x;
                    sA = fmaf(my_tanh(fmaf(cA.x, fA.y, fmaf(cA.y, fB.y, fC.y)) + qA.y), vv.y, sA);
                    sA = fmaf(my_tanh(fmaf(cA.x, fA.z, fmaf(cA.y, fB.z, fC.z)) + qA.z), vv.z, sA);
                    sA = fmaf(my_tanh(fmaf(cA.x, fA.w, fmaf(cA.y, fB.w, fC.w)) + qA.w), vv.w, sA);
                    #pragma unroll
                    for (int o = 16; o; o >>= 1) sA += __shfl_xor_sync(FULLMASK, sA, o);
                    if (lane == 0) sh_u[bA][nA] = 10.0f * my_tanh(sA);
                }
            }
        }
        __syncthreads();
        // ---- P9: log_softmax / softmax / argmax / outputs / state
        if (wid < Gg) {
            int b = wid; int gb = b0 + b;
            float l0 = sh_u[b][lane];
            float l1 = (lane < 18) ? sh_u[b][lane + 32] : -1e38f;
            float m = fmaxf(l0, l1);
            #pragma unroll
            for (int o = 16; o; o >>= 1) m = fmaxf(m, __shfl_xor_sync(FULLMASK, m, o));
            float e0 = __expf(l0 - m);
            float e1 = (lane < 18) ? __expf(l1 - m) : 0.f;
            float s = e0 + e1;
            #pragma unroll
            for (int o = 16; o; o >>= 1) s += __shfl_xor_sync(FULLMASK, s, o);
            float lgs = logf(s);
            float p0 = e0 / s;
            float p1 = e1 / s;
            size_t base = ((size_t)gb * Tt + t) * Nn;
            oLP[base + lane] = (l0 - m) - lgs;
            oP [base + lane] = p0;
            if (lane < 18) {
                oLP[base + lane + 32] = (l1 - m) - lgs;
                oP [base + lane + 32] = p1;
            }
            float bv = p0; int bi = lane;
            if (lane < 18 && p1 > bv) { bv = p1; bi = lane + 32; }
            #pragma unroll
            for (int o = 16; o; o >>= 1) {
                float ov = __shfl_down_sync(FULLMASK, bv, o);
                int   oi = __shfl_down_sync(FULLMASK, bi, o);
                if (ov > bv || (ov == bv && oi < bi)) { bv = ov; bi = oi; }
            }
            if (lane == 0) {
                int a = bi;
                sh_act[b] = a;
                sh_mask[b][a] = 1.0f;
                oA[(size_t)gb * Tt + t] = (float)a;
                float2 cc = sh_p[b][a];
                oC[((size_t)gb * Tt + t) * 2 + 0] = cc.x;
                oC[((size_t)gb * Tt + t) * 2 + 1] = cc.y;
                if (t == 0) { sh_fx[b] = cc.x; sh_fy[b] = cc.y; }
                else {
                    float dx = cc.x - sh_px[b], dy = cc.y - sh_py[b];
                    sh_R[b] += sqrtf(dx * dx + dy * dy + 1e-10f);
                }
                sh_px[b] = cc.x; sh_py[b] = cc.y;
            }
        }
        __syncthreads();
    } // t loop

    // ---- R closing edge
    if (tid < Gg) {
        int b = tid; int gb = b0 + b;
        float dx = sh_fx[b] - sh_px[b], dy = sh_fy[b] - sh_py[b];
        oR[gb] = sh_R[b] + sqrtf(dx * dx + dy * dy + 1e-10f);
    }
    __syncthreads();
    // ---- critic shortcut: hy = dec_last @ Wref_c, factored through (px,py,1)
    {
        int b = half;
        sh_q[b][jj] = fmaf(sh_px[b], g_frc[jj],
                      fmaf(sh_py[b], g_frc[128 + jj], g_frc[256 + jj]));
    }
    __syncthreads();
    {
        int b = half;
        float za = 0.f, zb = 0.f;
        #pragma unroll 4
        for (int k = 0; k < 128; k += 2) {
            za = fmaf(W1[k * 128 + jj],       sh_q[b][k],     za);
            zb = fmaf(W1[(k + 1) * 128 + jj], sh_q[b][k + 1], zb);
        }
        sh_q2[b][jj] = fmaxf(za + zb + b1[jj], 0.f);
    }
    __syncthreads();
    if (wid < Gg) {
        int b = wid; int gb = b0 + b;
        float4 zq = reinterpret_cast<const float4*>(sh_q2[b])[lane];
        float4 w2 = reinterpret_cast<const float4*>(W2)[lane];
        float s = zq.x * w2.x + zq.y * w2.y + zq.z * w2.z + zq.w * w2.w;
        #pragma unroll
        for (int o = 16; o; o >>= 1) s += __shfl_xor_sync(FULLMASK, s, o);
        if (lane == 0) oV[gb] = s + b2[0];
    }
}

extern "C" void kernel_launch(void* const* d_in, const int* in_sizes, int n_in,
                              void* d_out, int out_size) {
    const float* pnt  = (const float*)d_in[0];
    const float* Wemb = (const float*)d_in[1];
    const float* bemb = (const float*)d_in[2];
    const float* dini = (const float*)d_in[3];
    const float* Wi   = (const float*)d_in[4];
    const float* Wh   = (const float*)d_in[5];
    const float* bl   = (const float*)d_in[6];
    const float* Wqg  = (const float*)d_in[7];
    const float* Wrg  = (const float*)d_in[8];
    const float* vg   = (const float*)d_in[9];
    const float* Wqp  = (const float*)d_in[10];
    const float* Wrp  = (const float*)d_in[11];
    const float* vp   = (const float*)d_in[12];
    // d_in[13..16]: Wi_c, Wh_c, b_c, Wq_c — dead (softmax over length-1 enc)
    const float* Wrc  = (const float*)d_in[17];
    // d_in[18]: v_c — dead
    const float* W1   = (const float*)d_in[19];
    const float* b1   = (const float*)d_in[20];
    const float* W2   = (const float*)d_in[21];
    const float* b2   = (const float*)d_in[22];

    k_pre2<<<1, 512>>>(Wemb, bemb, Wrg, Wrp, Wi, Wqp, Wrc, dini);
    k_main<<<Bq / Gg, 256>>>(pnt, Wh, bl, Wqg, vg, vp,
                             W1, b1, W2, b2, (float*)d_out);
}